// round 15
// baseline (speedup 1.0000x reference)
#include <cuda_runtime.h>
#include <cuda_bf16.h>
#include <math.h>
#include <stdint.h>

#define N_NODES 50000
#define N_EDGES 400000
#define D_EMB   512
#define HEADS   8
#define DK      32
#define DV      32
#define HD      (HEADS * DK)   // 256
#define KQVS    768            // merged packed row: [h:K32|V32]x8 | Q 256

#define M_SPLIT 25088          // 196 tiles of 128; half B = 24912 rows (195 tiles)

// ---------------- scratch (device globals; no allocations allowed) ----------
__device__ float g_bkqv[KQVS];
__device__ int   g_cnt[N_NODES];
__device__ int   g_off[N_NODES + 1];
__device__ int   g_cur[N_NODES];
__device__ int   g_csr[N_EDGES];               // sender ids grouped by receiver
__device__ __nv_bfloat16 g_kqvb[N_NODES * KQVS];   // packed bf16 K|V per head, then Q
__device__ __nv_bfloat16 g_xb[N_NODES * D_EMB];
__device__ __nv_bfloat16 g_aggb[N_NODES * HD];
__device__ __nv_bfloat16 g_h1b[N_NODES * D_EMB];
__device__ __nv_bfloat16 g_wtb[786432];        // W^T bf16: kqv(perm) | Wa | Wf

#define OFF_WKQV 0
#define OFF_WA   393216
#define OFF_WF   524288

// ---------------- CSR build --------------------------------------------------
__global__ void zero_cnt_kernel() {
    int i = blockIdx.x * blockDim.x + threadIdx.x;
    if (i < N_NODES) g_cnt[i] = 0;
}
__global__ void hist_kernel(const int* __restrict__ ei) {
    int e = blockIdx.x * blockDim.x + threadIdx.x;
    if (e >= N_EDGES) return;
    atomicAdd(&g_cnt[ei[e]], 1);
}
__global__ __launch_bounds__(1024)
void scan_kernel() {
    __shared__ int partial[1024];
    const int t  = threadIdx.x;
    const int CH = (N_NODES + 1023) / 1024;   // 49
    const int base = t * CH;
    int sum = 0;
    for (int i = 0; i < CH; i++) {
        int idx = base + i;
        if (idx < N_NODES) sum += g_cnt[idx];
    }
    partial[t] = sum;
    __syncthreads();
    for (int d = 1; d < 1024; d <<= 1) {
        int v = (t >= d) ? partial[t - d] : 0;
        __syncthreads();
        partial[t] += v;
        __syncthreads();
    }
    int run = (t > 0) ? partial[t - 1] : 0;
    for (int i = 0; i < CH; i++) {
        int idx = base + i;
        if (idx < N_NODES) {
            int c = g_cnt[idx];
            g_off[idx] = run;
            g_cur[idx] = run;
            run += c;
        }
    }
    if (t == 1023) g_off[N_NODES] = partial[1023];
}
__global__ void place_kernel(const int* __restrict__ ei) {
    int e = blockIdx.x * blockDim.x + threadIdx.x;
    if (e >= N_EDGES) return;
    int r = ei[e];
    int s = ei[N_EDGES + e];
    int pos = atomicAdd(&g_cur[r], 1);
    g_csr[pos] = s;
}

// ---------------- prep: ALL weights -> gWtb [n][k] bf16 (one launch) ---------
__global__ void wt_all_cvt_kernel(const float* __restrict__ Wk,
                                  const float* __restrict__ Wq,
                                  const float* __restrict__ Wv,
                                  const float* __restrict__ Wa,
                                  const float* __restrict__ Wf) {
    int j = blockIdx.x * blockDim.x + threadIdx.x;
    if (j >= 786432) return;
    float v;
    if (j < 393216) {                 // kqv: rows 768, cols 512
        int n = j >> 9;               // j / 512
        int k = j & 511;
        if (n < 512) {
            int h = n >> 6, r = n & 63;
            v = (r < 32) ? Wk[(size_t)k * 256 + h * 32 + r]
                         : Wv[(size_t)k * 256 + h * 32 + (r - 32)];
        } else {
            v = Wq[(size_t)k * 256 + (n - 512)];
        }
    } else if (j < 524288) {          // Wa^T: rows 512, cols 256
        int jj = j - 393216;
        int n = jj >> 8;
        int k = jj & 255;
        v = Wa[(size_t)k * 512 + n];
    } else {                          // Wf^T: rows 512, cols 512
        int jj = j - 524288;
        int n = jj >> 9;
        int k = jj & 511;
        v = Wf[(size_t)k * 512 + n];
    }
    g_wtb[j] = __float2bfloat16_rn(v);
}

__global__ void cvt_bf16_kernel(const float* __restrict__ src,
                                __nv_bfloat16* __restrict__ dst, int n4) {
    int i = blockIdx.x * blockDim.x + threadIdx.x;
    if (i >= n4) return;
    float4 v = *(const float4*)(src + i * 4);
    __nv_bfloat162 a = __float22bfloat162_rn(make_float2(v.x, v.y));
    __nv_bfloat162 b = __float22bfloat162_rn(make_float2(v.z, v.w));
    *(uint32_t*)(dst + i * 4)     = *(uint32_t*)&a;
    *(uint32_t*)(dst + i * 4 + 2) = *(uint32_t*)&b;
}

__global__ void bias_concat_kernel(const float* bk, const float* bq,
                                   const float* bv) {
    int n = threadIdx.x + blockIdx.x * blockDim.x;
    if (n >= KQVS) return;
    float v;
    if (n < 512) {
        int h = n >> 6, r = n & 63;
        v = (r < 32) ? bk[h * 32 + r] : bv[h * 32 + (r - 32)];
    } else {
        v = bq[n - 512];
    }
    g_bkqv[n] = v;
}

// ---------------- bf16 GEMM: cp.async 4-stage + ldmatrix ---------------------
#define STAGES 4
#define KTILE  32
#define RS     40
#define AE     (128 * RS)
#define STE    (2 * AE)
#define GEMM_SMEM (STAGES * STE * 2)  // 81920 bytes

template<bool RELU_OUT, bool OUT_BF16, bool RES>
__global__ __launch_bounds__(256, 2)
void bf16gemm(const __nv_bfloat16* __restrict__ A,
              const __nv_bfloat16* __restrict__ B,
              const float* __restrict__ bias, const float* __restrict__ res,
              void* __restrict__ Cv, int M, int N, int K)
{
    extern __shared__ __nv_bfloat16 S[];
    const uint32_t sbase = (uint32_t)__cvta_generic_to_shared(S);

    const int tid  = threadIdx.x;
    const int lane = tid & 31;
    const int wid  = tid >> 5;
    const int wm   = (wid & 1) * 64;
    const int wn   = (wid >> 1) * 32;

    const int row0 = blockIdx.y * 128;
    const int col0 = blockIdx.x * 128;

    const int fr = lane >> 2;
    const int fc = lane & 3;

    const int a_off = (lane & 15) * RS + ((lane >> 4) << 3);
    const int b_off = (((lane >> 4) << 3) + (lane & 7)) * RS +
                      (((lane >> 3) & 1) << 3);

    float acc[4][4][4];
    #pragma unroll
    for (int mi = 0; mi < 4; mi++)
        #pragma unroll
        for (int ni = 0; ni < 4; ni++)
            #pragma unroll
            for (int q = 0; q < 4; q++) acc[mi][ni][q] = 0.0f;

    const int KT = K / KTILE;

    auto issue = [&](int t, int st) {
        int k0 = t * KTILE;
        #pragma unroll
        for (int i = 0; i < 2; i++) {
            int id = tid + i * 256;
            int r  = id >> 2;
            int c  = id & 3;
            {
                const __nv_bfloat16* src = A + (size_t)(row0 + r) * K + k0 + c * 8;
                uint32_t dst = sbase + (uint32_t)(st * STE + r * RS) * 2 + c * 16;
                int sz = (row0 + r < M) ? 16 : 0;
                asm volatile("cp.async.cg.shared.global [%0], [%1], 16, %2;"
                             :: "r"(dst), "l"(src), "r"(sz));
            }
            {
                const __nv_bfloat16* src = B + (size_t)(col0 + r) * K + k0 + c * 8;
                uint32_t dst = sbase + (uint32_t)(st * STE + AE + r * RS) * 2 + c * 16;
                asm volatile("cp.async.cg.shared.global [%0], [%1], 16, %2;"
                             :: "r"(dst), "l"(src), "r"(16));
            }
        }
    };

    auto compute = [&](int st) {
        const uint32_t aBase = sbase + (uint32_t)(st * STE) * 2;
        const uint32_t bBase = sbase + (uint32_t)(st * STE + AE) * 2;
        #pragma unroll
        for (int ks = 0; ks < KTILE; ks += 16) {
            uint32_t af[4][4];
            #pragma unroll
            for (int mi = 0; mi < 4; mi++) {
                uint32_t addr = aBase +
                    (uint32_t)((wm + mi * 16) * RS + ks + a_off) * 2;
                asm volatile(
                    "ldmatrix.sync.aligned.m8n8.x4.shared.b16 "
                    "{%0,%1,%2,%3}, [%4];"
                    : "=r"(af[mi][0]), "=r"(af[mi][1]),
                      "=r"(af[mi][2]), "=r"(af[mi][3])
                    : "r"(addr));
            }
            uint32_t bfr[4][2];
            #pragma unroll
            for (int p = 0; p < 2; p++) {
                uint32_t addr = bBase +
                    (uint32_t)((wn + p * 16) * RS + ks + b_off) * 2;
                asm volatile(
                    "ldmatrix.sync.aligned.m8n8.x4.shared.b16 "
                    "{%0,%1,%2,%3}, [%4];"
                    : "=r"(bfr[2 * p][0]), "=r"(bfr[2 * p][1]),
                      "=r"(bfr[2 * p + 1][0]), "=r"(bfr[2 * p + 1][1])
                    : "r"(addr));
            }
            #pragma unroll
            for (int mi = 0; mi < 4; mi++)
                #pragma unroll
                for (int ni = 0; ni < 4; ni++) {
                    float* d = acc[mi][ni];
                    asm volatile(
                        "mma.sync.aligned.m16n8k16.row.col.f32.bf16.bf16.f32 "
                        "{%0,%1,%2,%3},{%4,%5,%6,%7},{%8,%9},{%0,%1,%2,%3};"
                        : "+f"(d[0]), "+f"(d[1]), "+f"(d[2]), "+f"(d[3])
                        : "r"(af[mi][0]), "r"(af[mi][1]),
                          "r"(af[mi][2]), "r"(af[mi][3]),
                          "r"(bfr[ni][0]), "r"(bfr[ni][1]));
                }
        }
    };

    issue(0, 0);
    asm volatile("cp.async.commit_group;" ::: "memory");
    issue(1, 1);
    asm volatile("cp.async.commit_group;" ::: "memory");
    issue(2, 2);
    asm volatile("cp.async.commit_group;" ::: "memory");

    for (int t4 = 0; t4 < KT; t4 += 4) {
        #pragma unroll
        for (int s = 0; s < 4; s++) {
            int t = t4 + s;
            asm volatile("cp.async.wait_group 2;" ::: "memory");
            __syncthreads();
            if (t + 3 < KT) issue(t + 3, (s + 3) & 3);
            asm volatile("cp.async.commit_group;" ::: "memory");
            compute(s);
        }
    }

    #pragma unroll
    for (int mi = 0; mi < 4; mi++) {
        #pragma unroll
        for (int half = 0; half < 2; half++) {
            int gr = row0 + wm + mi * 16 + fr + half * 8;
            if (gr >= M) continue;
            #pragma unroll
            for (int ni = 0; ni < 4; ni++) {
                int gc = col0 + wn + ni * 8 + 2 * fc;
                float2 v;
                v.x = acc[mi][ni][half * 2 + 0] + bias[gc + 0];
                v.y = acc[mi][ni][half * 2 + 1] + bias[gc + 1];
                if (RELU_OUT) {
                    v.x = fmaxf(v.x, 0.f);
                    v.y = fmaxf(v.y, 0.f);
                }
                if (RES) {
                    float2 r = *(const float2*)(res + (size_t)gr * N + gc);
                    v.x += r.x; v.y += r.y;
                }
                if (OUT_BF16) {
                    __nv_bfloat162 h = __float22bfloat162_rn(v);
                    *(uint32_t*)((__nv_bfloat16*)Cv + (size_t)gr * N + gc) =
                        *(uint32_t*)&h;
                } else {
                    *(float2*)((float*)Cv + (size_t)gr * N + gc) = v;
                }
            }
        }
    }
}

// ---------------- fused edge gather (bf16, packed K|V, 2 edges/warp) ---------
// round-13 version: best measured. 16-lane halves, one edge per half.
__device__ __forceinline__ float2 bf2f(uint32_t u) {
    return __bfloat1622float2(*(__nv_bfloat162*)&u);
}

__global__ __launch_bounds__(256)
void edge_gather_kernel(const __nv_bfloat16* __restrict__ KQV,
                        int r0, int nNodes)
{
    int w = (blockIdx.x * blockDim.x + threadIdx.x) >> 5;
    if (w >= nNodes * HEADS) return;
    const int lane = threadIdx.x & 31;
    const int sub  = lane & 15;
    const int half = lane >> 4;
    const unsigned hmask = half ? 0xFFFF0000u : 0x0000FFFFu;
    const int r = (w >> 3) + r0;
    const int h = w & 7;

    uint2 qraw = *(const uint2*)(KQV + (size_t)r * KQVS + 512 + h * 32 +
                                 (sub & 7) * 4);
    const float2 qa = bf2f(qraw.x);
    const float2 qb = bf2f(qraw.y);
    const bool kSub = sub < 8;

    const int beg = g_off[r];
    const int end = g_off[r + 1];
    const size_t ecol = h * 64 + sub * 4;   // sub<8: K quad, sub>=8: V quad

    float denom = 0.f;
    float4 acc = make_float4(0.f, 0.f, 0.f, 0.f);

    int i = beg + half;
    for (; i + 2 < end; i += 4) {           // edges i and i+2 for this half
        int sA = g_csr[i];
        int sB = g_csr[i + 2];
        uint2 rA = *(const uint2*)(KQV + (size_t)sA * KQVS + ecol);
        uint2 rB = *(const uint2*)(KQV + (size_t)sB * KQVS + ecol);
        float2 aA = bf2f(rA.x), bA = bf2f(rA.y);
        float2 aB = bf2f(rB.x), bB = bf2f(rB.y);
        float dA = 0.f, dB = 0.f;
        if (kSub) {
            dA = fmaf(qb.y, bA.y, fmaf(qb.x, bA.x,
                 fmaf(qa.y, aA.y, qa.x * aA.x)));
            dB = fmaf(qb.y, bB.y, fmaf(qb.x, bB.x,
                 fmaf(qa.y, aB.y, qa.x * aB.x)));
        }
        #pragma unroll
        for (int m = 8; m; m >>= 1) {
            dA += __shfl_xor_sync(hmask, dA, m);
            dB += __shfl_xor_sync(hmask, dB, m);
        }
        float wA = __expf(dA * 0.17677669529663688f);
        float wB = __expf(dB * 0.17677669529663688f);
        denom += wA;
        acc.x = fmaf(wA, aA.x, acc.x); acc.y = fmaf(wA, aA.y, acc.y);
        acc.z = fmaf(wA, bA.x, acc.z); acc.w = fmaf(wA, bA.y, acc.w);
        denom += wB;
        acc.x = fmaf(wB, aB.x, acc.x); acc.y = fmaf(wB, aB.y, acc.y);
        acc.z = fmaf(wB, bB.x, acc.z); acc.w = fmaf(wB, bB.y, acc.w);
    }
    for (; i < end; i += 2) {
        int s = g_csr[i];
        uint2 raw = *(const uint2*)(KQV + (size_t)s * KQVS + ecol);
        float2 a = bf2f(raw.x), b = bf2f(raw.y);
        float d = 0.f;
        if (kSub)
            d = fmaf(qb.y, b.y, fmaf(qb.x, b.x, fmaf(qa.y, a.y, qa.x * a.x)));
        #pragma unroll
        for (int m = 8; m; m >>= 1)
            d += __shfl_xor_sync(hmask, d, m);
        float wg = __expf(d * 0.17677669529663688f);
        denom += wg;
        acc.x = fmaf(wg, a.x, acc.x); acc.y = fmaf(wg, a.y, acc.y);
        acc.z = fmaf(wg, b.x, acc.z); acc.w = fmaf(wg, b.y, acc.w);
    }

    __syncwarp();
    denom += __shfl_xor_sync(0xffffffffu, denom, 16);
    acc.x += __shfl_xor_sync(0xffffffffu, acc.x, 16);
    acc.y += __shfl_xor_sync(0xffffffffu, acc.y, 16);
    acc.z += __shfl_xor_sync(0xffffffffu, acc.z, 16);
    acc.w += __shfl_xor_sync(0xffffffffu, acc.w, 16);

    if (half == 0 && sub >= 8) {
        float4 o;
        if (denom > 0.f) {
            float inv = 1.0f / denom;
            o.x = fmaxf(acc.x * inv, 0.f);
            o.y = fmaxf(acc.y * inv, 0.f);
            o.z = fmaxf(acc.z * inv, 0.f);
            o.w = fmaxf(acc.w * inv, 0.f);
        } else {
            o = make_float4(0.f, 0.f, 0.f, 0.f);
        }
        __nv_bfloat162 h0 = __float22bfloat162_rn(make_float2(o.x, o.y));
        __nv_bfloat162 h1 = __float22bfloat162_rn(make_float2(o.z, o.w));
        uint2 pk = make_uint2(*(uint32_t*)&h0, *(uint32_t*)&h1);
        *(uint2*)(g_aggb + (size_t)r * HD + h * 32 + (sub - 8) * 4) = pk;
    }
}

// ---------------- launch ----------------------------------------------------
extern "C" void kernel_launch(void* const* d_in, const int* in_sizes, int n_in,
                              void* d_out, int out_size)
{
    const float* x  = (const float*)d_in[0];
    const int*   ei = (const int*)d_in[1];
    const float* Wk = (const float*)d_in[2];
    const float* bk = (const float*)d_in[3];
    const float* Wq = (const float*)d_in[4];
    const float* bq = (const float*)d_in[5];
    const float* Wv = (const float*)d_in[6];
    const float* bv = (const float*)d_in[7];
    const float* Wa = (const float*)d_in[8];
    const float* ba = (const float*)d_in[9];
    const float* Wf = (const float*)d_in[10];
    const float* bf = (const float*)d_in[11];
    float* out = (float*)d_out;

    float *gBkqv;
    __nv_bfloat16 *gKQVb, *gXb, *gAggb, *gH1b, *gWtb;
    cudaGetSymbolAddress((void**)&gBkqv, g_bkqv);
    cudaGetSymbolAddress((void**)&gKQVb, g_kqvb);
    cudaGetSymbolAddress((void**)&gXb,   g_xb);
    cudaGetSymbolAddress((void**)&gAggb, g_aggb);
    cudaGetSymbolAddress((void**)&gH1b,  g_h1b);
    cudaGetSymbolAddress((void**)&gWtb,  g_wtb);

    cudaFuncSetAttribute(bf16gemm<false, true, false>,
                         cudaFuncAttributeMaxDynamicSharedMemorySize, GEMM_SMEM);
    cudaFuncSetAttribute(bf16gemm<true, true, false>,
                         cudaFuncAttributeMaxDynamicSharedMemorySize, GEMM_SMEM);
    cudaFuncSetAttribute(bf16gemm<true, false, true>,
                         cudaFuncAttributeMaxDynamicSharedMemorySize, GEMM_SMEM);

    static cudaStream_t s1 = nullptr;
    static cudaEvent_t evFork = nullptr, evW = nullptr, evCSR = nullptr,
                       evGA = nullptr, evS1 = nullptr;
    if (s1 == nullptr) {
        cudaStreamCreate(&s1);
        cudaEventCreateWithFlags(&evFork, cudaEventDisableTiming);
        cudaEventCreateWithFlags(&evW,    cudaEventDisableTiming);
        cudaEventCreateWithFlags(&evCSR,  cudaEventDisableTiming);
        cudaEventCreateWithFlags(&evGA,   cudaEventDisableTiming);
        cudaEventCreateWithFlags(&evS1,   cudaEventDisableTiming);
    }

    const int MT  = (N_NODES + 127) / 128;   // 391 row tiles
    const int MTA = M_SPLIT / 128;           // 196
    const int MTB = MT - MTA;                // 195
    const int NA  = M_SPLIT;                 // 25088 rows (half A)
    const int NB  = N_NODES - M_SPLIT;       // 24912 rows (half B)

    // ---- fork: weight prep + CSR build on s1; x cvt on s0
    cudaEventRecord(evFork, 0);
    cudaStreamWaitEvent(s1, evFork, 0);
    wt_all_cvt_kernel<<<(786432 + 255) / 256, 256, 0, s1>>>(Wk, Wq, Wv, Wa, Wf);
    bias_concat_kernel<<<3, 256, 0, s1>>>(bk, bq, bv);
    cudaEventRecord(evW, s1);
    zero_cnt_kernel<<<(N_NODES + 255) / 256, 256, 0, s1>>>();
    hist_kernel<<<(N_EDGES + 255) / 256, 256, 0, s1>>>(ei);
    scan_kernel<<<1, 1024, 0, s1>>>();
    place_kernel<<<(N_EDGES + 255) / 256, 256, 0, s1>>>(ei);
    cudaEventRecord(evCSR, s1);

    cvt_bf16_kernel<<<(N_NODES * D_EMB / 4 + 255) / 256, 256>>>(x, gXb,
                                                                N_NODES * D_EMB / 4);

    // ---- KQV projection (needs weights from s1)
    cudaStreamWaitEvent(0, evW, 0);
    dim3 gProj(KQVS / 128, MT);                     // (6, 391)
    bf16gemm<false, true, false><<<gProj, 256, GEMM_SMEM>>>(
        gXb, gWtb + OFF_WKQV, gBkqv, nullptr, gKQVb, N_NODES, KQVS, D_EMB);

    // ---- join CSR, then split-M pipelined tail chain
    cudaStreamWaitEvent(0, evCSR, 0);

    // gather half A on s0, signal s1
    edge_gather_kernel<<<(NA * HEADS * 32 + 255) / 256, 256>>>(gKQVb, 0, NA);
    cudaEventRecord(evGA, 0);

    // s1: attn-out A + ffn A (overlaps gather B / attn-out B on s0)
    cudaStreamWaitEvent(s1, evGA, 0);
    dim3 gAa(D_EMB / 128, MTA);
    bf16gemm<true, true, false><<<gAa, 256, GEMM_SMEM, s1>>>(
        gAggb, gWtb + OFF_WA, ba, nullptr, gH1b, NA, D_EMB, HD);
    dim3 gFa(D_EMB / 128, MTA);
    bf16gemm<true, false, true><<<gFa, 256, GEMM_SMEM, s1>>>(
        gH1b, gWtb + OFF_WF, bf, x, out, NA, D_EMB, D_EMB);
    cudaEventRecord(evS1, s1);

    // s0: gather B, attn-out B, ffn B
    edge_gather_kernel<<<(NB * HEADS * 32 + 255) / 256, 256>>>(gKQVb, NA, NB);
    dim3 gAb(D_EMB / 128, MTB);
    bf16gemm<true, true, false><<<gAb, 256, GEMM_SMEM>>>(
        gAggb + (size_t)NA * HD, gWtb + OFF_WA, ba, nullptr,
        gH1b + (size_t)NA * D_EMB, NB, D_EMB, HD);
    dim3 gFb(D_EMB / 128, MTB);
    bf16gemm<true, false, true><<<gFb, 256, GEMM_SMEM>>>(
        gH1b + (size_t)NA * D_EMB, gWtb + OFF_WF, bf,
        x + (size_t)NA * D_EMB, out + (size_t)NA * D_EMB, NB, D_EMB, D_EMB);

    // join s1 back before capture ends
    cudaStreamWaitEvent(0, evS1, 0);
}

// round 16
// speedup vs baseline: 1.1305x; 1.1305x over previous
#include <cuda_runtime.h>
#include <cuda_bf16.h>
#include <math.h>
#include <stdint.h>

#define N_NODES 50000
#define N_EDGES 400000
#define D_EMB   512
#define HEADS   8
#define DK      32
#define DV      32
#define HD      (HEADS * DK)   // 256
#define KQVS    768            // merged packed row: [h:K32|V32]x8 | Q 256

#define M_SPLIT 25088          // 196 tiles of 128; half B = 24912 rows (195 tiles)

// ---------------- scratch (device globals; no allocations allowed) ----------
__device__ float g_bkqv[KQVS];
__device__ int   g_cnt[N_NODES];
__device__ int   g_off[N_NODES + 1];
__device__ int   g_cur[N_NODES];
__device__ int   g_csr[N_EDGES];               // sender ids grouped by receiver
__device__ __nv_bfloat16 g_kqvb[N_NODES * KQVS];   // packed bf16 K|V per head, then Q
__device__ __nv_bfloat16 g_xb[N_NODES * D_EMB];
__device__ __nv_bfloat16 g_aggb[N_NODES * HD];
__device__ __nv_bfloat16 g_h1b[N_NODES * D_EMB];
__device__ __nv_bfloat16 g_wtb[786432];        // W^T bf16: kqv(perm) | Wa | Wf

#define OFF_WKQV 0
#define OFF_WA   393216
#define OFF_WF   524288

// ---------------- CSR build --------------------------------------------------
__global__ void zero_cnt_kernel() {
    int i = blockIdx.x * blockDim.x + threadIdx.x;
    if (i < N_NODES) g_cnt[i] = 0;
}
__global__ void hist_kernel(const int* __restrict__ ei) {
    int e = blockIdx.x * blockDim.x + threadIdx.x;
    if (e >= N_EDGES) return;
    atomicAdd(&g_cnt[ei[e]], 1);
}
__global__ __launch_bounds__(1024)
void scan_kernel() {
    __shared__ int partial[1024];
    const int t  = threadIdx.x;
    const int CH = (N_NODES + 1023) / 1024;   // 49
    const int base = t * CH;
    int sum = 0;
    for (int i = 0; i < CH; i++) {
        int idx = base + i;
        if (idx < N_NODES) sum += g_cnt[idx];
    }
    partial[t] = sum;
    __syncthreads();
    for (int d = 1; d < 1024; d <<= 1) {
        int v = (t >= d) ? partial[t - d] : 0;
        __syncthreads();
        partial[t] += v;
        __syncthreads();
    }
    int run = (t > 0) ? partial[t - 1] : 0;
    for (int i = 0; i < CH; i++) {
        int idx = base + i;
        if (idx < N_NODES) {
            int c = g_cnt[idx];
            g_off[idx] = run;
            g_cur[idx] = run;
            run += c;
        }
    }
    if (t == 1023) g_off[N_NODES] = partial[1023];
}
__global__ void place_kernel(const int* __restrict__ ei) {
    int e = blockIdx.x * blockDim.x + threadIdx.x;
    if (e >= N_EDGES) return;
    int r = ei[e];
    int s = ei[N_EDGES + e];
    int pos = atomicAdd(&g_cur[r], 1);
    g_csr[pos] = s;
}

// ---------------- prep: ALL weights + bias -> bf16 (one launch) --------------
// j in [0, 786432): weights into g_wtb (kqv permuted-packed | Wa^T | Wf^T)
// j in [786432, 787200): packed kqv bias into g_bkqv
__global__ void wt_all_cvt_kernel(const float* __restrict__ Wk,
                                  const float* __restrict__ Wq,
                                  const float* __restrict__ Wv,
                                  const float* __restrict__ Wa,
                                  const float* __restrict__ Wf,
                                  const float* __restrict__ bk,
                                  const float* __restrict__ bq,
                                  const float* __restrict__ bv) {
    int j = blockIdx.x * blockDim.x + threadIdx.x;
    if (j >= 786432 + KQVS) return;
    if (j >= 786432) {                // packed kqv bias
        int n = j - 786432;
        float v;
        if (n < 512) {
            int h = n >> 6, r = n & 63;
            v = (r < 32) ? bk[h * 32 + r] : bv[h * 32 + (r - 32)];
        } else {
            v = bq[n - 512];
        }
        g_bkqv[n] = v;
        return;
    }
    float v;
    if (j < 393216) {                 // kqv: rows 768, cols 512
        int n = j >> 9;               // j / 512
        int k = j & 511;
        if (n < 512) {
            int h = n >> 6, r = n & 63;
            v = (r < 32) ? Wk[(size_t)k * 256 + h * 32 + r]
                         : Wv[(size_t)k * 256 + h * 32 + (r - 32)];
        } else {
            v = Wq[(size_t)k * 256 + (n - 512)];
        }
    } else if (j < 524288) {          // Wa^T: rows 512, cols 256
        int jj = j - 393216;
        int n = jj >> 8;
        int k = jj & 255;
        v = Wa[(size_t)k * 512 + n];
    } else {                          // Wf^T: rows 512, cols 512
        int jj = j - 524288;
        int n = jj >> 9;
        int k = jj & 511;
        v = Wf[(size_t)k * 512 + n];
    }
    g_wtb[j] = __float2bfloat16_rn(v);
}

__global__ void cvt_bf16_kernel(const float* __restrict__ src,
                                __nv_bfloat16* __restrict__ dst, int n4) {
    int i = blockIdx.x * blockDim.x + threadIdx.x;
    if (i >= n4) return;
    float4 v = *(const float4*)(src + i * 4);
    __nv_bfloat162 a = __float22bfloat162_rn(make_float2(v.x, v.y));
    __nv_bfloat162 b = __float22bfloat162_rn(make_float2(v.z, v.w));
    *(uint32_t*)(dst + i * 4)     = *(uint32_t*)&a;
    *(uint32_t*)(dst + i * 4 + 2) = *(uint32_t*)&b;
}

// ---------------- bf16 GEMM: cp.async 4-stage + ldmatrix ---------------------
#define STAGES 4
#define KTILE  32
#define RS     40
#define AE     (128 * RS)
#define STE    (2 * AE)
#define GEMM_SMEM (STAGES * STE * 2)  // 81920 bytes

template<bool RELU_OUT, bool OUT_BF16, bool RES>
__global__ __launch_bounds__(256, 2)
void bf16gemm(const __nv_bfloat16* __restrict__ A,
              const __nv_bfloat16* __restrict__ B,
              const float* __restrict__ bias, const float* __restrict__ res,
              void* __restrict__ Cv, int M, int N, int K)
{
    extern __shared__ __nv_bfloat16 S[];
    const uint32_t sbase = (uint32_t)__cvta_generic_to_shared(S);

    const int tid  = threadIdx.x;
    const int lane = tid & 31;
    const int wid  = tid >> 5;
    const int wm   = (wid & 1) * 64;
    const int wn   = (wid >> 1) * 32;

    const int row0 = blockIdx.y * 128;
    const int col0 = blockIdx.x * 128;

    const int fr = lane >> 2;
    const int fc = lane & 3;

    const int a_off = (lane & 15) * RS + ((lane >> 4) << 3);
    const int b_off = (((lane >> 4) << 3) + (lane & 7)) * RS +
                      (((lane >> 3) & 1) << 3);

    float acc[4][4][4];
    #pragma unroll
    for (int mi = 0; mi < 4; mi++)
        #pragma unroll
        for (int ni = 0; ni < 4; ni++)
            #pragma unroll
            for (int q = 0; q < 4; q++) acc[mi][ni][q] = 0.0f;

    const int KT = K / KTILE;

    auto issue = [&](int t, int st) {
        int k0 = t * KTILE;
        #pragma unroll
        for (int i = 0; i < 2; i++) {
            int id = tid + i * 256;
            int r  = id >> 2;
            int c  = id & 3;
            {
                const __nv_bfloat16* src = A + (size_t)(row0 + r) * K + k0 + c * 8;
                uint32_t dst = sbase + (uint32_t)(st * STE + r * RS) * 2 + c * 16;
                int sz = (row0 + r < M) ? 16 : 0;
                asm volatile("cp.async.cg.shared.global [%0], [%1], 16, %2;"
                             :: "r"(dst), "l"(src), "r"(sz));
            }
            {
                const __nv_bfloat16* src = B + (size_t)(col0 + r) * K + k0 + c * 8;
                uint32_t dst = sbase + (uint32_t)(st * STE + AE + r * RS) * 2 + c * 16;
                asm volatile("cp.async.cg.shared.global [%0], [%1], 16, %2;"
                             :: "r"(dst), "l"(src), "r"(16));
            }
        }
    };

    auto compute = [&](int st) {
        const uint32_t aBase = sbase + (uint32_t)(st * STE) * 2;
        const uint32_t bBase = sbase + (uint32_t)(st * STE + AE) * 2;
        #pragma unroll
        for (int ks = 0; ks < KTILE; ks += 16) {
            uint32_t af[4][4];
            #pragma unroll
            for (int mi = 0; mi < 4; mi++) {
                uint32_t addr = aBase +
                    (uint32_t)((wm + mi * 16) * RS + ks + a_off) * 2;
                asm volatile(
                    "ldmatrix.sync.aligned.m8n8.x4.shared.b16 "
                    "{%0,%1,%2,%3}, [%4];"
                    : "=r"(af[mi][0]), "=r"(af[mi][1]),
                      "=r"(af[mi][2]), "=r"(af[mi][3])
                    : "r"(addr));
            }
            uint32_t bfr[4][2];
            #pragma unroll
            for (int p = 0; p < 2; p++) {
                uint32_t addr = bBase +
                    (uint32_t)((wn + p * 16) * RS + ks + b_off) * 2;
                asm volatile(
                    "ldmatrix.sync.aligned.m8n8.x4.shared.b16 "
                    "{%0,%1,%2,%3}, [%4];"
                    : "=r"(bfr[2 * p][0]), "=r"(bfr[2 * p][1]),
                      "=r"(bfr[2 * p + 1][0]), "=r"(bfr[2 * p + 1][1])
                    : "r"(addr));
            }
            #pragma unroll
            for (int mi = 0; mi < 4; mi++)
                #pragma unroll
                for (int ni = 0; ni < 4; ni++) {
                    float* d = acc[mi][ni];
                    asm volatile(
                        "mma.sync.aligned.m16n8k16.row.col.f32.bf16.bf16.f32 "
                        "{%0,%1,%2,%3},{%4,%5,%6,%7},{%8,%9},{%0,%1,%2,%3};"
                        : "+f"(d[0]), "+f"(d[1]), "+f"(d[2]), "+f"(d[3])
                        : "r"(af[mi][0]), "r"(af[mi][1]),
                          "r"(af[mi][2]), "r"(af[mi][3]),
                          "r"(bfr[ni][0]), "r"(bfr[ni][1]));
                }
        }
    };

    issue(0, 0);
    asm volatile("cp.async.commit_group;" ::: "memory");
    issue(1, 1);
    asm volatile("cp.async.commit_group;" ::: "memory");
    issue(2, 2);
    asm volatile("cp.async.commit_group;" ::: "memory");

    for (int t4 = 0; t4 < KT; t4 += 4) {
        #pragma unroll
        for (int s = 0; s < 4; s++) {
            int t = t4 + s;
            asm volatile("cp.async.wait_group 2;" ::: "memory");
            __syncthreads();
            if (t + 3 < KT) issue(t + 3, (s + 3) & 3);
            asm volatile("cp.async.commit_group;" ::: "memory");
            compute(s);
        }
    }

    #pragma unroll
    for (int mi = 0; mi < 4; mi++) {
        #pragma unroll
        for (int half = 0; half < 2; half++) {
            int gr = row0 + wm + mi * 16 + fr + half * 8;
            if (gr >= M) continue;
            #pragma unroll
            for (int ni = 0; ni < 4; ni++) {
                int gc = col0 + wn + ni * 8 + 2 * fc;
                float2 v;
                v.x = acc[mi][ni][half * 2 + 0] + bias[gc + 0];
                v.y = acc[mi][ni][half * 2 + 1] + bias[gc + 1];
                if (RELU_OUT) {
                    v.x = fmaxf(v.x, 0.f);
                    v.y = fmaxf(v.y, 0.f);
                }
                if (RES) {
                    float2 r = *(const float2*)(res + (size_t)gr * N + gc);
                    v.x += r.x; v.y += r.y;
                }
                if (OUT_BF16) {
                    __nv_bfloat162 h = __float22bfloat162_rn(v);
                    *(uint32_t*)((__nv_bfloat16*)Cv + (size_t)gr * N + gc) =
                        *(uint32_t*)&h;
                } else {
                    *(float2*)((float*)Cv + (size_t)gr * N + gc) = v;
                }
            }
        }
    }
}

// ---------------- fused edge gather (bf16, packed K|V, 2 edges/warp) ---------
// 16-lane halves, one edge per half (best measured configuration).
__device__ __forceinline__ float2 bf2f(uint32_t u) {
    return __bfloat1622float2(*(__nv_bfloat162*)&u);
}

__global__ __launch_bounds__(256)
void edge_gather_kernel(const __nv_bfloat16* __restrict__ KQV,
                        int r0, int nNodes)
{
    int w = (blockIdx.x * blockDim.x + threadIdx.x) >> 5;
    if (w >= nNodes * HEADS) return;
    const int lane = threadIdx.x & 31;
    const int sub  = lane & 15;
    const int half = lane >> 4;
    const unsigned hmask = half ? 0xFFFF0000u : 0x0000FFFFu;
    const int r = (w >> 3) + r0;
    const int h = w & 7;

    uint2 qraw = *(const uint2*)(KQV + (size_t)r * KQVS + 512 + h * 32 +
                                 (sub & 7) * 4);
    const float2 qa = bf2f(qraw.x);
    const float2 qb = bf2f(qraw.y);
    const bool kSub = sub < 8;

    const int beg = g_off[r];
    const int end = g_off[r + 1];
    const size_t ecol = h * 64 + sub * 4;   // sub<8: K quad, sub>=8: V quad

    float denom = 0.f;
    float4 acc = make_float4(0.f, 0.f, 0.f, 0.f);

    int i = beg + half;
    for (; i + 2 < end; i += 4) {           // edges i and i+2 for this half
        int sA = g_csr[i];
        int sB = g_csr[i + 2];
        uint2 rA = *(const uint2*)(KQV + (size_t)sA * KQVS + ecol);
        uint2 rB = *(const uint2*)(KQV + (size_t)sB * KQVS + ecol);
        float2 aA = bf2f(rA.x), bA = bf2f(rA.y);
        float2 aB = bf2f(rB.x), bB = bf2f(rB.y);
        float dA = 0.f, dB = 0.f;
        if (kSub) {
            dA = fmaf(qb.y, bA.y, fmaf(qb.x, bA.x,
                 fmaf(qa.y, aA.y, qa.x * aA.x)));
            dB = fmaf(qb.y, bB.y, fmaf(qb.x, bB.x,
                 fmaf(qa.y, aB.y, qa.x * aB.x)));
        }
        #pragma unroll
        for (int m = 8; m; m >>= 1) {
            dA += __shfl_xor_sync(hmask, dA, m);
            dB += __shfl_xor_sync(hmask, dB, m);
        }
        float wA = __expf(dA * 0.17677669529663688f);
        float wB = __expf(dB * 0.17677669529663688f);
        denom += wA;
        acc.x = fmaf(wA, aA.x, acc.x); acc.y = fmaf(wA, aA.y, acc.y);
        acc.z = fmaf(wA, bA.x, acc.z); acc.w = fmaf(wA, bA.y, acc.w);
        denom += wB;
        acc.x = fmaf(wB, aB.x, acc.x); acc.y = fmaf(wB, aB.y, acc.y);
        acc.z = fmaf(wB, bB.x, acc.z); acc.w = fmaf(wB, bB.y, acc.w);
    }
    for (; i < end; i += 2) {
        int s = g_csr[i];
        uint2 raw = *(const uint2*)(KQV + (size_t)s * KQVS + ecol);
        float2 a = bf2f(raw.x), b = bf2f(raw.y);
        float d = 0.f;
        if (kSub)
            d = fmaf(qb.y, b.y, fmaf(qb.x, b.x, fmaf(qa.y, a.y, qa.x * a.x)));
        #pragma unroll
        for (int m = 8; m; m >>= 1)
            d += __shfl_xor_sync(hmask, d, m);
        float wg = __expf(d * 0.17677669529663688f);
        denom += wg;
        acc.x = fmaf(wg, a.x, acc.x); acc.y = fmaf(wg, a.y, acc.y);
        acc.z = fmaf(wg, b.x, acc.z); acc.w = fmaf(wg, b.y, acc.w);
    }

    __syncwarp();
    denom += __shfl_xor_sync(0xffffffffu, denom, 16);
    acc.x += __shfl_xor_sync(0xffffffffu, acc.x, 16);
    acc.y += __shfl_xor_sync(0xffffffffu, acc.y, 16);
    acc.z += __shfl_xor_sync(0xffffffffu, acc.z, 16);
    acc.w += __shfl_xor_sync(0xffffffffu, acc.w, 16);

    if (half == 0 && sub >= 8) {
        float4 o;
        if (denom > 0.f) {
            float inv = 1.0f / denom;
            o.x = fmaxf(acc.x * inv, 0.f);
            o.y = fmaxf(acc.y * inv, 0.f);
            o.z = fmaxf(acc.z * inv, 0.f);
            o.w = fmaxf(acc.w * inv, 0.f);
        } else {
            o = make_float4(0.f, 0.f, 0.f, 0.f);
        }
        __nv_bfloat162 h0 = __float22bfloat162_rn(make_float2(o.x, o.y));
        __nv_bfloat162 h1 = __float22bfloat162_rn(make_float2(o.z, o.w));
        uint2 pk = make_uint2(*(uint32_t*)&h0, *(uint32_t*)&h1);
        *(uint2*)(g_aggb + (size_t)r * HD + h * 32 + (sub - 8) * 4) = pk;
    }
}

// ---------------- launch ----------------------------------------------------
extern "C" void kernel_launch(void* const* d_in, const int* in_sizes, int n_in,
                              void* d_out, int out_size)
{
    const float* x  = (const float*)d_in[0];
    const int*   ei = (const int*)d_in[1];
    const float* Wk = (const float*)d_in[2];
    const float* bk = (const float*)d_in[3];
    const float* Wq = (const float*)d_in[4];
    const float* bq = (const float*)d_in[5];
    const float* Wv = (const float*)d_in[6];
    const float* bv = (const float*)d_in[7];
    const float* Wa = (const float*)d_in[8];
    const float* ba = (const float*)d_in[9];
    const float* Wf = (const float*)d_in[10];
    const float* bf = (const float*)d_in[11];
    float* out = (float*)d_out;

    float *gBkqv;
    __nv_bfloat16 *gKQVb, *gXb, *gAggb, *gH1b, *gWtb;
    cudaGetSymbolAddress((void**)&gBkqv, g_bkqv);
    cudaGetSymbolAddress((void**)&gKQVb, g_kqvb);
    cudaGetSymbolAddress((void**)&gXb,   g_xb);
    cudaGetSymbolAddress((void**)&gAggb, g_aggb);
    cudaGetSymbolAddress((void**)&gH1b,  g_h1b);
    cudaGetSymbolAddress((void**)&gWtb,  g_wtb);

    cudaFuncSetAttribute(bf16gemm<false, true, false>,
                         cudaFuncAttributeMaxDynamicSharedMemorySize, GEMM_SMEM);
    cudaFuncSetAttribute(bf16gemm<true, true, false>,
                         cudaFuncAttributeMaxDynamicSharedMemorySize, GEMM_SMEM);
    cudaFuncSetAttribute(bf16gemm<true, false, true>,
                         cudaFuncAttributeMaxDynamicSharedMemorySize, GEMM_SMEM);

    static cudaStream_t s1 = nullptr;
    static cudaEvent_t evFork = nullptr, evCSR = nullptr,
                       evGA = nullptr, evS1 = nullptr;
    if (s1 == nullptr) {
        cudaStreamCreate(&s1);
        cudaEventCreateWithFlags(&evFork, cudaEventDisableTiming);
        cudaEventCreateWithFlags(&evCSR,  cudaEventDisableTiming);
        cudaEventCreateWithFlags(&evGA,   cudaEventDisableTiming);
        cudaEventCreateWithFlags(&evS1,   cudaEventDisableTiming);
    }

    const int MT  = (N_NODES + 127) / 128;   // 391 row tiles
    const int MTA = M_SPLIT / 128;           // 196
    const int MTB = MT - MTA;                // 195
    const int NA  = M_SPLIT;                 // 25088 rows (half A)
    const int NB  = N_NODES - M_SPLIT;       // 24912 rows (half B)

    // ---- fork: CSR build on s1 (runs under s0's memory-light prep), prep on s0
    cudaEventRecord(evFork, 0);
    cudaStreamWaitEvent(s1, evFork, 0);
    zero_cnt_kernel<<<(N_NODES + 255) / 256, 256, 0, s1>>>();
    hist_kernel<<<(N_EDGES + 255) / 256, 256, 0, s1>>>(ei);
    scan_kernel<<<1, 1024, 0, s1>>>();
    place_kernel<<<(N_EDGES + 255) / 256, 256, 0, s1>>>(ei);
    cudaEventRecord(evCSR, s1);

    wt_all_cvt_kernel<<<(786432 + KQVS + 255) / 256, 256>>>(Wk, Wq, Wv, Wa, Wf,
                                                            bk, bq, bv);
    cvt_bf16_kernel<<<(N_NODES * D_EMB / 4 + 255) / 256, 256>>>(x, gXb,
                                                                N_NODES * D_EMB / 4);

    dim3 gProj(KQVS / 128, MT);                     // (6, 391)
    bf16gemm<false, true, false><<<gProj, 256, GEMM_SMEM>>>(
        gXb, gWtb + OFF_WKQV, gBkqv, nullptr, gKQVb, N_NODES, KQVS, D_EMB);

    // ---- join CSR, then split-M pipelined tail chain
    cudaStreamWaitEvent(0, evCSR, 0);

    // gather half A on s0, signal s1
    edge_gather_kernel<<<(NA * HEADS * 32 + 255) / 256, 256>>>(gKQVb, 0, NA);
    cudaEventRecord(evGA, 0);

    // s1: attn-out A + ffn A (overlaps gather B / attn-out B on s0)
    cudaStreamWaitEvent(s1, evGA, 0);
    dim3 gAa(D_EMB / 128, MTA);
    bf16gemm<true, true, false><<<gAa, 256, GEMM_SMEM, s1>>>(
        gAggb, gWtb + OFF_WA, ba, nullptr, gH1b, NA, D_EMB, HD);
    dim3 gFa(D_EMB / 128, MTA);
    bf16gemm<true, false, true><<<gFa, 256, GEMM_SMEM, s1>>>(
        gH1b, gWtb + OFF_WF, bf, x, out, NA, D_EMB, D_EMB);
    cudaEventRecord(evS1, s1);

    // s0: gather B, attn-out B, ffn B
    edge_gather_kernel<<<(NB * HEADS * 32 + 255) / 256, 256>>>(gKQVb, NA, NB);
    dim3 gAb(D_EMB / 128, MTB);
    bf16gemm<true, true, false><<<gAb, 256, GEMM_SMEM>>>(
        gAggb + (size_t)NA * HD, gWtb + OFF_WA, ba, nullptr,
        gH1b + (size_t)NA * D_EMB, NB, D_EMB, HD);
    dim3 gFb(D_EMB / 128, MTB);
    bf16gemm<true, false, true><<<gFb, 256, GEMM_SMEM>>>(
        gH1b + (size_t)NA * D_EMB, gWtb + OFF_WF, bf,
        x + (size_t)NA * D_EMB, out + (size_t)NA * D_EMB, NB, D_EMB, D_EMB);

    // join s1 back before capture ends
    cudaStreamWaitEvent(0, evS1, 0);
}

// round 17
// speedup vs baseline: 1.1965x; 1.0584x over previous
#include <cuda_runtime.h>
#include <cuda_bf16.h>
#include <math.h>
#include <stdint.h>

#define N_NODES 50000
#define N_EDGES 400000
#define D_EMB   512
#define HEADS   8
#define DK      32
#define DV      32
#define HD      (HEADS * DK)   // 256
#define KQVS    768            // merged packed row: [h:K32|V32]x8 | Q 256

#define M_SPLIT 25088          // 196 tiles of 128; half B = 24912 rows (195 tiles)

// ---------------- scratch (device globals; no allocations allowed) ----------
__device__ float g_bkqv[KQVS];
__device__ int   g_cnt[N_NODES];
__device__ int   g_off[N_NODES + 1];
__device__ int   g_cur[N_NODES];
__device__ int   g_csr[N_EDGES];               // sender ids grouped by receiver
__device__ __nv_bfloat16 g_kqvb[N_NODES * KQVS];   // packed bf16 K|V per head, then Q
__device__ __nv_bfloat16 g_xb[N_NODES * D_EMB];
__device__ __nv_bfloat16 g_aggb[N_NODES * HD];
__device__ __nv_bfloat16 g_h1b[N_NODES * D_EMB];
__device__ __nv_bfloat16 g_wtb[786432];        // W^T bf16: kqv(perm) | Wa | Wf

#define OFF_WKQV 0
#define OFF_WA   393216
#define OFF_WF   524288

// ---------------- CSR build --------------------------------------------------
__global__ void zero_cnt_kernel() {
    int i = blockIdx.x * blockDim.x + threadIdx.x;
    if (i < N_NODES) g_cnt[i] = 0;
}
__global__ void hist_kernel(const int* __restrict__ ei) {
    int e = blockIdx.x * blockDim.x + threadIdx.x;
    if (e >= N_EDGES) return;
    atomicAdd(&g_cnt[ei[e]], 1);
}
__global__ __launch_bounds__(1024)
void scan_kernel() {
    __shared__ int partial[1024];
    const int t  = threadIdx.x;
    const int CH = (N_NODES + 1023) / 1024;   // 49
    const int base = t * CH;
    int sum = 0;
    for (int i = 0; i < CH; i++) {
        int idx = base + i;
        if (idx < N_NODES) sum += g_cnt[idx];
    }
    partial[t] = sum;
    __syncthreads();
    for (int d = 1; d < 1024; d <<= 1) {
        int v = (t >= d) ? partial[t - d] : 0;
        __syncthreads();
        partial[t] += v;
        __syncthreads();
    }
    int run = (t > 0) ? partial[t - 1] : 0;
    for (int i = 0; i < CH; i++) {
        int idx = base + i;
        if (idx < N_NODES) {
            int c = g_cnt[idx];
            g_off[idx] = run;
            g_cur[idx] = run;
            run += c;
        }
    }
    if (t == 1023) g_off[N_NODES] = partial[1023];
}
__global__ void place_kernel(const int* __restrict__ ei) {
    int e = blockIdx.x * blockDim.x + threadIdx.x;
    if (e >= N_EDGES) return;
    int r = ei[e];
    int s = ei[N_EDGES + e];
    int pos = atomicAdd(&g_cur[r], 1);
    g_csr[pos] = s;
}

// ---------------- prep: ALL weights -> gWtb [n][k] bf16 (one launch) ---------
__global__ void wt_all_cvt_kernel(const float* __restrict__ Wk,
                                  const float* __restrict__ Wq,
                                  const float* __restrict__ Wv,
                                  const float* __restrict__ Wa,
                                  const float* __restrict__ Wf) {
    int j = blockIdx.x * blockDim.x + threadIdx.x;
    if (j >= 786432) return;
    float v;
    if (j < 393216) {                 // kqv: rows 768, cols 512
        int n = j >> 9;               // j / 512
        int k = j & 511;
        if (n < 512) {
            int h = n >> 6, r = n & 63;
            v = (r < 32) ? Wk[(size_t)k * 256 + h * 32 + r]
                         : Wv[(size_t)k * 256 + h * 32 + (r - 32)];
        } else {
            v = Wq[(size_t)k * 256 + (n - 512)];
        }
    } else if (j < 524288) {          // Wa^T: rows 512, cols 256
        int jj = j - 393216;
        int n = jj >> 8;
        int k = jj & 255;
        v = Wa[(size_t)k * 512 + n];
    } else {                          // Wf^T: rows 512, cols 512
        int jj = j - 524288;
        int n = jj >> 9;
        int k = jj & 511;
        v = Wf[(size_t)k * 512 + n];
    }
    g_wtb[j] = __float2bfloat16_rn(v);
}

__global__ void cvt_bf16_kernel(const float* __restrict__ src,
                                __nv_bfloat16* __restrict__ dst, int n4) {
    int i = blockIdx.x * blockDim.x + threadIdx.x;
    if (i >= n4) return;
    float4 v = *(const float4*)(src + i * 4);
    __nv_bfloat162 a = __float22bfloat162_rn(make_float2(v.x, v.y));
    __nv_bfloat162 b = __float22bfloat162_rn(make_float2(v.z, v.w));
    *(uint32_t*)(dst + i * 4)     = *(uint32_t*)&a;
    *(uint32_t*)(dst + i * 4 + 2) = *(uint32_t*)&b;
}

__global__ void bias_concat_kernel(const float* bk, const float* bq,
                                   const float* bv) {
    int n = threadIdx.x + blockIdx.x * blockDim.x;
    if (n >= KQVS) return;
    float v;
    if (n < 512) {
        int h = n >> 6, r = n & 63;
        v = (r < 32) ? bk[h * 32 + r] : bv[h * 32 + (r - 32)];
    } else {
        v = bq[n - 512];
    }
    g_bkqv[n] = v;
}

// ---------------- bf16 GEMM: cp.async 4-stage + ldmatrix ---------------------
#define STAGES 4
#define KTILE  32
#define RS     40
#define AE     (128 * RS)
#define STE    (2 * AE)
#define GEMM_SMEM (STAGES * STE * 2)  // 81920 bytes

template<bool RELU_OUT, bool OUT_BF16, bool RES>
__global__ __launch_bounds__(256, 2)
void bf16gemm(const __nv_bfloat16* __restrict__ A,
              const __nv_bfloat16* __restrict__ B,
              const float* __restrict__ bias, const float* __restrict__ res,
              void* __restrict__ Cv, int M, int N, int K)
{
    extern __shared__ __nv_bfloat16 S[];
    const uint32_t sbase = (uint32_t)__cvta_generic_to_shared(S);

    const int tid  = threadIdx.x;
    const int lane = tid & 31;
    const int wid  = tid >> 5;
    const int wm   = (wid & 1) * 64;
    const int wn   = (wid >> 1) * 32;

    const int row0 = blockIdx.y * 128;
    const int col0 = blockIdx.x * 128;

    const int fr = lane >> 2;
    const int fc = lane & 3;

    const int a_off = (lane & 15) * RS + ((lane >> 4) << 3);
    const int b_off = (((lane >> 4) << 3) + (lane & 7)) * RS +
                      (((lane >> 3) & 1) << 3);

    float acc[4][4][4];
    #pragma unroll
    for (int mi = 0; mi < 4; mi++)
        #pragma unroll
        for (int ni = 0; ni < 4; ni++)
            #pragma unroll
            for (int q = 0; q < 4; q++) acc[mi][ni][q] = 0.0f;

    const int KT = K / KTILE;

    auto issue = [&](int t, int st) {
        int k0 = t * KTILE;
        #pragma unroll
        for (int i = 0; i < 2; i++) {
            int id = tid + i * 256;
            int r  = id >> 2;
            int c  = id & 3;
            {
                const __nv_bfloat16* src = A + (size_t)(row0 + r) * K + k0 + c * 8;
                uint32_t dst = sbase + (uint32_t)(st * STE + r * RS) * 2 + c * 16;
                int sz = (row0 + r < M) ? 16 : 0;
                asm volatile("cp.async.cg.shared.global [%0], [%1], 16, %2;"
                             :: "r"(dst), "l"(src), "r"(sz));
            }
            {
                const __nv_bfloat16* src = B + (size_t)(col0 + r) * K + k0 + c * 8;
                uint32_t dst = sbase + (uint32_t)(st * STE + AE + r * RS) * 2 + c * 16;
                asm volatile("cp.async.cg.shared.global [%0], [%1], 16, %2;"
                             :: "r"(dst), "l"(src), "r"(16));
            }
        }
    };

    auto compute = [&](int st) {
        const uint32_t aBase = sbase + (uint32_t)(st * STE) * 2;
        const uint32_t bBase = sbase + (uint32_t)(st * STE + AE) * 2;
        #pragma unroll
        for (int ks = 0; ks < KTILE; ks += 16) {
            uint32_t af[4][4];
            #pragma unroll
            for (int mi = 0; mi < 4; mi++) {
                uint32_t addr = aBase +
                    (uint32_t)((wm + mi * 16) * RS + ks + a_off) * 2;
                asm volatile(
                    "ldmatrix.sync.aligned.m8n8.x4.shared.b16 "
                    "{%0,%1,%2,%3}, [%4];"
                    : "=r"(af[mi][0]), "=r"(af[mi][1]),
                      "=r"(af[mi][2]), "=r"(af[mi][3])
                    : "r"(addr));
            }
            uint32_t bfr[4][2];
            #pragma unroll
            for (int p = 0; p < 2; p++) {
                uint32_t addr = bBase +
                    (uint32_t)((wn + p * 16) * RS + ks + b_off) * 2;
                asm volatile(
                    "ldmatrix.sync.aligned.m8n8.x4.shared.b16 "
                    "{%0,%1,%2,%3}, [%4];"
                    : "=r"(bfr[2 * p][0]), "=r"(bfr[2 * p][1]),
                      "=r"(bfr[2 * p + 1][0]), "=r"(bfr[2 * p + 1][1])
                    : "r"(addr));
            }
            #pragma unroll
            for (int mi = 0; mi < 4; mi++)
                #pragma unroll
                for (int ni = 0; ni < 4; ni++) {
                    float* d = acc[mi][ni];
                    asm volatile(
                        "mma.sync.aligned.m16n8k16.row.col.f32.bf16.bf16.f32 "
                        "{%0,%1,%2,%3},{%4,%5,%6,%7},{%8,%9},{%0,%1,%2,%3};"
                        : "+f"(d[0]), "+f"(d[1]), "+f"(d[2]), "+f"(d[3])
                        : "r"(af[mi][0]), "r"(af[mi][1]),
                          "r"(af[mi][2]), "r"(af[mi][3]),
                          "r"(bfr[ni][0]), "r"(bfr[ni][1]));
                }
        }
    };

    issue(0, 0);
    asm volatile("cp.async.commit_group;" ::: "memory");
    issue(1, 1);
    asm volatile("cp.async.commit_group;" ::: "memory");
    issue(2, 2);
    asm volatile("cp.async.commit_group;" ::: "memory");

    for (int t4 = 0; t4 < KT; t4 += 4) {
        #pragma unroll
        for (int s = 0; s < 4; s++) {
            int t = t4 + s;
            asm volatile("cp.async.wait_group 2;" ::: "memory");
            __syncthreads();
            if (t + 3 < KT) issue(t + 3, (s + 3) & 3);
            asm volatile("cp.async.commit_group;" ::: "memory");
            compute(s);
        }
    }

    #pragma unroll
    for (int mi = 0; mi < 4; mi++) {
        #pragma unroll
        for (int half = 0; half < 2; half++) {
            int gr = row0 + wm + mi * 16 + fr + half * 8;
            if (gr >= M) continue;
            #pragma unroll
            for (int ni = 0; ni < 4; ni++) {
                int gc = col0 + wn + ni * 8 + 2 * fc;
                float2 v;
                v.x = acc[mi][ni][half * 2 + 0] + bias[gc + 0];
                v.y = acc[mi][ni][half * 2 + 1] + bias[gc + 1];
                if (RELU_OUT) {
                    v.x = fmaxf(v.x, 0.f);
                    v.y = fmaxf(v.y, 0.f);
                }
                if (RES) {
                    float2 r = *(const float2*)(res + (size_t)gr * N + gc);
                    v.x += r.x; v.y += r.y;
                }
                if (OUT_BF16) {
                    __nv_bfloat162 h = __float22bfloat162_rn(v);
                    *(uint32_t*)((__nv_bfloat16*)Cv + (size_t)gr * N + gc) =
                        *(uint32_t*)&h;
                } else {
                    *(float2*)((float*)Cv + (size_t)gr * N + gc) = v;
                }
            }
        }
    }
}

// ---------------- fused edge gather (bf16, packed K|V, 2 edges/warp) ---------
// 16-lane halves, one edge per half (best measured configuration).
__device__ __forceinline__ float2 bf2f(uint32_t u) {
    return __bfloat1622float2(*(__nv_bfloat162*)&u);
}

__global__ __launch_bounds__(256)
void edge_gather_kernel(const __nv_bfloat16* __restrict__ KQV,
                        int r0, int nNodes)
{
    int w = (blockIdx.x * blockDim.x + threadIdx.x) >> 5;
    if (w >= nNodes * HEADS) return;
    const int lane = threadIdx.x & 31;
    const int sub  = lane & 15;
    const int half = lane >> 4;
    const unsigned hmask = half ? 0xFFFF0000u : 0x0000FFFFu;
    const int r = (w >> 3) + r0;
    const int h = w & 7;

    uint2 qraw = *(const uint2*)(KQV + (size_t)r * KQVS + 512 + h * 32 +
                                 (sub & 7) * 4);
    const float2 qa = bf2f(qraw.x);
    const float2 qb = bf2f(qraw.y);
    const bool kSub = sub < 8;

    const int beg = g_off[r];
    const int end = g_off[r + 1];
    const size_t ecol = h * 64 + sub * 4;   // sub<8: K quad, sub>=8: V quad

    float denom = 0.f;
    float4 acc = make_float4(0.f, 0.f, 0.f, 0.f);

    int i = beg + half;
    for (; i + 2 < end; i += 4) {           // edges i and i+2 for this half
        int sA = g_csr[i];
        int sB = g_csr[i + 2];
        uint2 rA = *(const uint2*)(KQV + (size_t)sA * KQVS + ecol);
        uint2 rB = *(const uint2*)(KQV + (size_t)sB * KQVS + ecol);
        float2 aA = bf2f(rA.x), bA = bf2f(rA.y);
        float2 aB = bf2f(rB.x), bB = bf2f(rB.y);
        float dA = 0.f, dB = 0.f;
        if (kSub) {
            dA = fmaf(qb.y, bA.y, fmaf(qb.x, bA.x,
                 fmaf(qa.y, aA.y, qa.x * aA.x)));
            dB = fmaf(qb.y, bB.y, fmaf(qb.x, bB.x,
                 fmaf(qa.y, aB.y, qa.x * aB.x)));
        }
        #pragma unroll
        for (int m = 8; m; m >>= 1) {
            dA += __shfl_xor_sync(hmask, dA, m);
            dB += __shfl_xor_sync(hmask, dB, m);
        }
        float wA = __expf(dA * 0.17677669529663688f);
        float wB = __expf(dB * 0.17677669529663688f);
        denom += wA;
        acc.x = fmaf(wA, aA.x, acc.x); acc.y = fmaf(wA, aA.y, acc.y);
        acc.z = fmaf(wA, bA.x, acc.z); acc.w = fmaf(wA, bA.y, acc.w);
        denom += wB;
        acc.x = fmaf(wB, aB.x, acc.x); acc.y = fmaf(wB, aB.y, acc.y);
        acc.z = fmaf(wB, bB.x, acc.z); acc.w = fmaf(wB, bB.y, acc.w);
    }
    for (; i < end; i += 2) {
        int s = g_csr[i];
        uint2 raw = *(const uint2*)(KQV + (size_t)s * KQVS + ecol);
        float2 a = bf2f(raw.x), b = bf2f(raw.y);
        float d = 0.f;
        if (kSub)
            d = fmaf(qb.y, b.y, fmaf(qb.x, b.x, fmaf(qa.y, a.y, qa.x * a.x)));
        #pragma unroll
        for (int m = 8; m; m >>= 1)
            d += __shfl_xor_sync(hmask, d, m);
        float wg = __expf(d * 0.17677669529663688f);
        denom += wg;
        acc.x = fmaf(wg, a.x, acc.x); acc.y = fmaf(wg, a.y, acc.y);
        acc.z = fmaf(wg, b.x, acc.z); acc.w = fmaf(wg, b.y, acc.w);
    }

    __syncwarp();
    denom += __shfl_xor_sync(0xffffffffu, denom, 16);
    acc.x += __shfl_xor_sync(0xffffffffu, acc.x, 16);
    acc.y += __shfl_xor_sync(0xffffffffu, acc.y, 16);
    acc.z += __shfl_xor_sync(0xffffffffu, acc.z, 16);
    acc.w += __shfl_xor_sync(0xffffffffu, acc.w, 16);

    if (half == 0 && sub >= 8) {
        float4 o;
        if (denom > 0.f) {
            float inv = 1.0f / denom;
            o.x = fmaxf(acc.x * inv, 0.f);
            o.y = fmaxf(acc.y * inv, 0.f);
            o.z = fmaxf(acc.z * inv, 0.f);
            o.w = fmaxf(acc.w * inv, 0.f);
        } else {
            o = make_float4(0.f, 0.f, 0.f, 0.f);
        }
        __nv_bfloat162 h0 = __float22bfloat162_rn(make_float2(o.x, o.y));
        __nv_bfloat162 h1 = __float22bfloat162_rn(make_float2(o.z, o.w));
        uint2 pk = make_uint2(*(uint32_t*)&h0, *(uint32_t*)&h1);
        *(uint2*)(g_aggb + (size_t)r * HD + h * 32 + (sub - 8) * 4) = pk;
    }
}

// ---------------- launch ----------------------------------------------------
extern "C" void kernel_launch(void* const* d_in, const int* in_sizes, int n_in,
                              void* d_out, int out_size)
{
    const float* x  = (const float*)d_in[0];
    const int*   ei = (const int*)d_in[1];
    const float* Wk = (const float*)d_in[2];
    const float* bk = (const float*)d_in[3];
    const float* Wq = (const float*)d_in[4];
    const float* bq = (const float*)d_in[5];
    const float* Wv = (const float*)d_in[6];
    const float* bv = (const float*)d_in[7];
    const float* Wa = (const float*)d_in[8];
    const float* ba = (const float*)d_in[9];
    const float* Wf = (const float*)d_in[10];
    const float* bf = (const float*)d_in[11];
    float* out = (float*)d_out;

    float *gBkqv;
    __nv_bfloat16 *gKQVb, *gXb, *gAggb, *gH1b, *gWtb;
    cudaGetSymbolAddress((void**)&gBkqv, g_bkqv);
    cudaGetSymbolAddress((void**)&gKQVb, g_kqvb);
    cudaGetSymbolAddress((void**)&gXb,   g_xb);
    cudaGetSymbolAddress((void**)&gAggb, g_aggb);
    cudaGetSymbolAddress((void**)&gH1b,  g_h1b);
    cudaGetSymbolAddress((void**)&gWtb,  g_wtb);

    cudaFuncSetAttribute(bf16gemm<false, true, false>,
                         cudaFuncAttributeMaxDynamicSharedMemorySize, GEMM_SMEM);
    cudaFuncSetAttribute(bf16gemm<true, true, false>,
                         cudaFuncAttributeMaxDynamicSharedMemorySize, GEMM_SMEM);
    cudaFuncSetAttribute(bf16gemm<true, false, true>,
                         cudaFuncAttributeMaxDynamicSharedMemorySize, GEMM_SMEM);

    static cudaStream_t s1 = nullptr;
    static cudaEvent_t evFork = nullptr, evCSR = nullptr,
                       evGA = nullptr, evS1 = nullptr;
    if (s1 == nullptr) {
        cudaStreamCreate(&s1);
        cudaEventCreateWithFlags(&evFork, cudaEventDisableTiming);
        cudaEventCreateWithFlags(&evCSR,  cudaEventDisableTiming);
        cudaEventCreateWithFlags(&evGA,   cudaEventDisableTiming);
        cudaEventCreateWithFlags(&evS1,   cudaEventDisableTiming);
    }

    const int MT  = (N_NODES + 127) / 128;   // 391 row tiles
    const int MTA = M_SPLIT / 128;           // 196
    const int MTB = MT - MTA;                // 195
    const int NA  = M_SPLIT;                 // 25088 rows (half A)
    const int NB  = N_NODES - M_SPLIT;       // 24912 rows (half B)

    // ---- fork: CSR build on s1, prep+KQV on s0
    cudaEventRecord(evFork, 0);
    cudaStreamWaitEvent(s1, evFork, 0);
    zero_cnt_kernel<<<(N_NODES + 255) / 256, 256, 0, s1>>>();
    hist_kernel<<<(N_EDGES + 255) / 256, 256, 0, s1>>>(ei);
    scan_kernel<<<1, 1024, 0, s1>>>();
    place_kernel<<<(N_EDGES + 255) / 256, 256, 0, s1>>>(ei);
    cudaEventRecord(evCSR, s1);

    wt_all_cvt_kernel<<<(786432 + 255) / 256, 256>>>(Wk, Wq, Wv, Wa, Wf);
    cvt_bf16_kernel<<<(N_NODES * D_EMB / 4 + 255) / 256, 256>>>(x, gXb,
                                                                N_NODES * D_EMB / 4);
    bias_concat_kernel<<<3, 256>>>(bk, bq, bv);

    dim3 gProj(KQVS / 128, MT);                     // (6, 391)
    bf16gemm<false, true, false><<<gProj, 256, GEMM_SMEM>>>(
        gXb, gWtb + OFF_WKQV, gBkqv, nullptr, gKQVb, N_NODES, KQVS, D_EMB);

    // ---- join CSR, then split-M pipelined tail chain
    cudaStreamWaitEvent(0, evCSR, 0);

    // gather half A on s0, signal s1
    edge_gather_kernel<<<(NA * HEADS * 32 + 255) / 256, 256>>>(gKQVb, 0, NA);
    cudaEventRecord(evGA, 0);

    // s1: attn-out A + ffn A (overlaps gather B / attn-out B on s0)
    cudaStreamWaitEvent(s1, evGA, 0);
    dim3 gAa(D_EMB / 128, MTA);
    bf16gemm<true, true, false><<<gAa, 256, GEMM_SMEM, s1>>>(
        gAggb, gWtb + OFF_WA, ba, nullptr, gH1b, NA, D_EMB, HD);
    dim3 gFa(D_EMB / 128, MTA);
    bf16gemm<true, false, true><<<gFa, 256, GEMM_SMEM, s1>>>(
        gH1b, gWtb + OFF_WF, bf, x, out, NA, D_EMB, D_EMB);
    cudaEventRecord(evS1, s1);

    // s0: gather B, attn-out B, ffn B
    edge_gather_kernel<<<(NB * HEADS * 32 + 255) / 256, 256>>>(gKQVb, NA, NB);
    dim3 gAb(D_EMB / 128, MTB);
    bf16gemm<true, true, false><<<gAb, 256, GEMM_SMEM>>>(
        gAggb + (size_t)NA * HD, gWtb + OFF_WA, ba, nullptr,
        gH1b + (size_t)NA * D_EMB, NB, D_EMB, HD);
    dim3 gFb(D_EMB / 128, MTB);
    bf16gemm<true, false, true><<<gFb, 256, GEMM_SMEM>>>(
        gH1b + (size_t)NA * D_EMB, gWtb + OFF_WF, bf,
        x + (size_t)NA * D_EMB, out + (size_t)NA * D_EMB, NB, D_EMB, D_EMB);

    // join s1 back before capture ends
    cudaStreamWaitEvent(0, evS1, 0);
}